// round 11
// baseline (speedup 1.0000x reference)
#include <cuda_runtime.h>
#include <cuda_fp16.h>
#include <cstdint>
#include <cstddef>
#include <cstring>

// Problem constants (fixed by the dataset)
constexpr int Gn = 16;
constexpr int Bn = 8192;
constexpr int Kn = 1024;
constexpr int Dn = 64;

constexpr int DP  = 80;              // augmented dim: 64 data + 4 norm + 12 pad
constexpr int RB  = DP * 2;          // 160 bytes per augmented row
constexpr int TM  = 128;             // x rows per tile
constexpr int TN  = 128;             // centroids per CTA (resident)
constexpr int NBT = 8;               // x tiles per CTA
constexpr int NT  = 512;             // threads per CTA

// Augmented f16 operands (device globals: allocation-free scratch).
//  x row:  [-2x (64)] [x2_hi, x2_lo, 1, 1] [0 x 12]
//  c row:  [ c  (64)] [1, 1, c2_hi, c2_lo] [0 x 12]
__device__ __align__(16) uint32_t g_xb[(size_t)Gn * Bn * (RB / 4)];
__device__ __align__(16) uint32_t g_cb[(size_t)Gn * Kn * (RB / 4)];

// Dynamic smem layout (bytes). Each tile slot = 16KB main (128B rows, XOR
// swizzle) + 4KB aug (32B rows). c resident + 3 x buffers (2-ahead prefetch).
constexpr int CS0 = 0;
constexpr int XBB = 20480;           // x buffer stride
constexpr int SMEM_TOTAL = 20480 * 4;   // 81920 B

__device__ __forceinline__ uint32_t smem_u32(const void* p) {
    uint32_t a;
    asm("{ .reg .u64 t; cvta.to.shared.u64 t, %1; cvt.u32.u64 %0, t; }"
        : "=r"(a) : "l"(p));
    return a;
}
__device__ __forceinline__ float fsqrt_approx(float v) {
    float r;
    asm("sqrt.approx.f32 %0, %1;" : "=f"(r) : "f"(v));
    return r;
}
__device__ __forceinline__ uint32_t pack_f16(float lo, float hi) {
    __half2 h = __floats2half2_rn(lo, hi);   // .x = lo (low half)
    uint32_t u;
    memcpy(&u, &h, 4);
    return u;
}
__device__ __forceinline__ void cp16(uint32_t dst, const void* src) {
    asm volatile("cp.async.cg.shared.global [%0], [%1], 16;"
                 :: "r"(dst), "l"(src) : "memory");
}
#define CP_COMMIT() asm volatile("cp.async.commit_group;" ::: "memory")
#define CP_WAIT0()  asm volatile("cp.async.wait_group 0;" ::: "memory")
#define CP_WAIT1()  asm volatile("cp.async.wait_group 1;" ::: "memory")

__device__ __forceinline__ void ldsm_x4(uint32_t r[4], uint32_t addr) {
    asm volatile("ldmatrix.sync.aligned.m8n8.x4.shared.b16 {%0,%1,%2,%3}, [%4];"
                 : "=r"(r[0]), "=r"(r[1]), "=r"(r[2]), "=r"(r[3]) : "r"(addr));
}
// f16 x f16 -> f16 accumulate: D/C in 2 regs (f16x2 each)
__device__ __forceinline__ void mma_f16(uint32_t c[2], const uint32_t a[4],
                                        uint32_t b0, uint32_t b1) {
    asm volatile(
        "mma.sync.aligned.m16n8k16.row.col.f16.f16.f16.f16 "
        "{%0,%1}, {%2,%3,%4,%5}, {%6,%7}, {%0,%1};"
        : "+r"(c[0]), "+r"(c[1])
        : "r"(a[0]), "r"(a[1]), "r"(a[2]), "r"(a[3]), "r"(b0), "r"(b1));
}
__device__ __forceinline__ void stg_cs2(float* p, float a, float b) {
    asm volatile("st.global.cs.v2.f32 [%0], {%1, %2};"
                 :: "l"(p), "f"(a), "f"(b) : "memory");
}
// aug-tile address: 32B rows; 16B chunk q of row r at flat=(2r+q)^((r>>2)&7)
__device__ __forceinline__ uint32_t t1addr(uint32_t base, int row, int q) {
    return base + (uint32_t)((((row * 2 + q) ^ ((row >> 2) & 7)) << 4));
}

// ---------------------------------------------------------------------------
// Pass 1: build augmented f16 rows (exact fp32 norms, f16 hi/lo split).
// ---------------------------------------------------------------------------
__global__ __launch_bounds__(256)
void prep_kernel(const float* __restrict__ x, const float* __restrict__ cen)
{
    const int t  = blockIdx.x * blockDim.x + threadIdx.x;
    const int NX = Gn * Bn;
    const int NC = Gn * Kn;
    const float4* src;
    uint4* dst;
    bool is_x;
    if (t < NX) {
        src = (const float4*)(x + (size_t)t * Dn);
        dst = (uint4*)(g_xb + (size_t)t * (RB / 4));
        is_x = true;
    } else if (t < NX + NC) {
        src = (const float4*)(cen + (size_t)(t - NX) * Dn);
        dst = (uint4*)(g_cb + (size_t)(t - NX) * (RB / 4));
        is_x = false;
    } else return;

    const float a = is_x ? -2.0f : 1.0f;
    float s = 0.f;
#pragma unroll
    for (int i = 0; i < 8; i++) {
        float4 v0 = src[2 * i];
        float4 v1 = src[2 * i + 1];
        s = fmaf(v0.x, v0.x, s); s = fmaf(v0.y, v0.y, s);
        s = fmaf(v0.z, v0.z, s); s = fmaf(v0.w, v0.w, s);
        s = fmaf(v1.x, v1.x, s); s = fmaf(v1.y, v1.y, s);
        s = fmaf(v1.z, v1.z, s); s = fmaf(v1.w, v1.w, s);
        uint4 o;
        o.x = pack_f16(a * v0.x, a * v0.y); o.y = pack_f16(a * v0.z, a * v0.w);
        o.z = pack_f16(a * v1.x, a * v1.y); o.w = pack_f16(a * v1.z, a * v1.w);
        dst[i] = o;
    }
    // f16 hi/lo split of the squared norm
    const float hf  = __half2float(__float2half_rn(s));
    const float res = s - hf;
    uint4 aug;
    if (is_x) { aug.x = pack_f16(hf, res);   aug.y = pack_f16(1.f, 1.f); }
    else      { aug.x = pack_f16(1.f, 1.f);  aug.y = pack_f16(hf, res);  }
    aug.z = 0u; aug.w = 0u;
    dst[8] = aug;
    dst[9] = make_uint4(0u, 0u, 0u, 0u);
}

// Tile loader: 1280 16B chunks (128 rows x 160B) over 512 threads.
// Slot layout: main at base, aug at base+16384.
__device__ __forceinline__ void load_tile(uint32_t base, const char* gsrc, int tid)
{
#pragma unroll
    for (int i = 0; i < 3; i++) {
        const int idx = i * NT + tid;
        if (idx < 1280) {
            const int row = idx / 10;
            const int q   = idx - row * 10;
            const char* src = gsrc + row * RB + q * 16;
            if (q < 8) cp16(base + row * 128 + ((q ^ (row & 7)) << 4), src);
            else       cp16(t1addr(base + 16384, row, q - 8), src);
        }
    }
}

// ---------------------------------------------------------------------------
// Pass 2: 512 threads, 4x4 warps of 32x32 tiles; f16 acc == d^2.
// Triple-buffered x tiles, 2-ahead cp.async prefetch.
// ---------------------------------------------------------------------------
__global__ __launch_bounds__(NT, 2)
void dist_kernel(float* __restrict__ out)
{
    extern __shared__ __align__(128) char smem[];
    const uint32_t sb = smem_u32(smem);

    const int tid  = threadIdx.x;
    const int wid  = tid >> 5;
    const int lane = tid & 31;
    const int qid  = lane >> 2;     // 0..7
    const int t4   = lane & 3;      // 0..3

    const int g     = blockIdx.z;
    const int k0    = blockIdx.x * TN;
    const int bslab = blockIdx.y * (TM * NBT);

    const char* cgb = (const char*)g_cb + (size_t)(g * Kn + k0)    * RB;
    const char* xgb = (const char*)g_xb + (size_t)(g * Bn + bslab) * RB;

    // ---- Prologue: group0 = {c, x0}; group1 = {x1}. ----
    load_tile(sb + CS0, cgb, tid);
    load_tile(sb + XBB, xgb, tid);
    CP_COMMIT();
    load_tile(sb + 2 * XBB, xgb + (size_t)TM * RB, tid);
    CP_COMMIT();

    const int wm = (wid >> 2) * 32;   // warp m-base: 0/32/64/96
    const int wn = (wid & 3) * 32;    // warp n-base: 0/32/64/96

    // Per-lane ldmatrix geometry.
    const int swz    = lane & 7;
    const int a_row  = lane & 15;                        // + wm + mt*16
    const int a_qoff = lane >> 4;                        // 0/1
    const int b_nrow = ((lane >> 4) << 3) + (lane & 7);  // + wn (+16)
    const int b_qoff = (lane >> 3) & 1;                  // 0/1

    const uint32_t cs0 = sb + CS0;
    const uint32_t cs1 = sb + CS0 + 16384;

    // Rotating x-buffer bases: cur = compute, nxt = next tile, pf = prefetch dst.
    uint32_t xcur = sb + XBB;
    uint32_t xnxt = sb + 2 * XBB;
    uint32_t xpf  = sb + 3 * XBB;

#pragma unroll 1
    for (int bt = 0; bt < NBT; bt++) {
        if (bt == NBT - 1) { CP_WAIT0(); } else { CP_WAIT1(); }
        __syncthreads();

        if (bt + 2 < NBT) {
            load_tile(xpf, xgb + (size_t)(bt + 2) * TM * RB, tid);
            CP_COMMIT();
        }

        const uint32_t xs0 = xcur;
        const uint32_t xs1 = xcur + 16384;

        // acc[mt][nt][h]: f16x2 pair; rows wm+16mt+8h+qid, cols wn+8nt+2t4.
        uint32_t acc[2][4][2];
#pragma unroll
        for (int mt = 0; mt < 2; mt++)
#pragma unroll
            for (int nt = 0; nt < 4; nt++) { acc[mt][nt][0] = 0u; acc[mt][nt][1] = 0u; }

        // ---- k-steps 0..3: main 64 dims. ----
#pragma unroll
        for (int ks = 0; ks < 4; ks++) {
            const uint32_t qa = (uint32_t)(((2 * ks + a_qoff) ^ swz) << 4);
            const uint32_t qb = (uint32_t)(((2 * ks + b_qoff) ^ swz) << 4);

            uint32_t bf[4][2];
            {
                uint32_t r[4];
                ldsm_x4(r, cs0 + (uint32_t)((wn + b_nrow) * 128) + qb);
                bf[0][0] = r[0]; bf[0][1] = r[1]; bf[1][0] = r[2]; bf[1][1] = r[3];
                ldsm_x4(r, cs0 + (uint32_t)((wn + 16 + b_nrow) * 128) + qb);
                bf[2][0] = r[0]; bf[2][1] = r[1]; bf[3][0] = r[2]; bf[3][1] = r[3];
            }
#pragma unroll
            for (int mt = 0; mt < 2; mt++) {
                uint32_t a[4];
                ldsm_x4(a, xs0 + (uint32_t)((wm + mt * 16 + a_row) * 128) + qa);
#pragma unroll
                for (int nt = 0; nt < 4; nt++)
                    mma_f16(acc[mt][nt], a, bf[nt][0], bf[nt][1]);
            }
        }

        // ---- k-step 4: augmented 16 dims. ----
        {
            uint32_t bf[4][2];
            {
                uint32_t r[4];
                ldsm_x4(r, t1addr(cs1, wn + b_nrow, b_qoff));
                bf[0][0] = r[0]; bf[0][1] = r[1]; bf[1][0] = r[2]; bf[1][1] = r[3];
                ldsm_x4(r, t1addr(cs1, wn + 16 + b_nrow, b_qoff));
                bf[2][0] = r[0]; bf[2][1] = r[1]; bf[3][0] = r[2]; bf[3][1] = r[3];
            }
#pragma unroll
            for (int mt = 0; mt < 2; mt++) {
                uint32_t a[4];
                ldsm_x4(a, t1addr(xs1, wm + mt * 16 + a_row, a_qoff));
#pragma unroll
                for (int nt = 0; nt < 4; nt++)
                    mma_f16(acc[mt][nt], a, bf[nt][0], bf[nt][1]);
            }
        }

        // ---- Epilogue: unpack f16 d^2 -> sqrt -> streaming store. ----
        const int b0 = bslab + bt * TM;
#pragma unroll
        for (int mt = 0; mt < 2; mt++) {
            const int row0 = b0 + wm + mt * 16 + qid;
            float* opa = out + (size_t)(g * Bn + row0) * Kn + k0 + wn + 2 * t4;
            float* opb = opa + (size_t)8 * Kn;
#pragma unroll
            for (int nt = 0; nt < 4; nt++) {
                __half2 h0, h1;
                memcpy(&h0, &acc[mt][nt][0], 4);
                memcpy(&h1, &acc[mt][nt][1], 4);
                float2 f0 = __half22float2(h0);   // row0:  cols 2t4, 2t4+1
                float2 f1 = __half22float2(h1);   // row0+8
                stg_cs2(opa + nt * 8, fsqrt_approx(f0.x), fsqrt_approx(f0.y));
                stg_cs2(opb + nt * 8, fsqrt_approx(f1.x), fsqrt_approx(f1.y));
            }
        }

        // Rotate x buffers.
        const uint32_t t = xcur;
        xcur = xnxt; xnxt = xpf; xpf = t;
    }
}

extern "C" void kernel_launch(void* const* d_in, const int* in_sizes, int n_in,
                              void* d_out, int out_size)
{
    const float* x   = (const float*)d_in[0];   // [G, B, D] fp32
    const float* cen = (const float*)d_in[1];   // [G, K, D] fp32
    float* out = (float*)d_out;                 // [G, B, K] fp32

    static bool attr_set = false;
    if (!attr_set) {
        cudaFuncSetAttribute(dist_kernel,
                             cudaFuncAttributeMaxDynamicSharedMemorySize, SMEM_TOTAL);
        attr_set = true;
    }

    const int nrows = Gn * Bn + Gn * Kn;
    prep_kernel<<<(nrows + 255) / 256, 256>>>(x, cen);

    dim3 grid(Kn / TN, Bn / (TM * NBT), Gn);    // (8, 8, 16) = 1024 CTAs
    dist_kernel<<<grid, NT, SMEM_TOTAL>>>(out);
}

// round 12
// speedup vs baseline: 1.0717x; 1.0717x over previous
#include <cuda_runtime.h>
#include <cuda_fp16.h>
#include <cstdint>
#include <cstddef>
#include <cstring>

// Problem constants (fixed by the dataset)
constexpr int Gn = 16;
constexpr int Bn = 8192;
constexpr int Kn = 1024;
constexpr int Dn = 64;

constexpr int DP  = 80;              // augmented dim: 64 data + 4 norm + 12 pad
constexpr int RB  = DP * 2;          // 160 bytes per augmented row
constexpr int TM  = 128;             // x rows per CTA (resident)
constexpr int TN  = 128;             // centroids per tile (streamed)
constexpr int NCT = Kn / TN;         // 8 c tiles per CTA
constexpr int NT  = 512;             // threads per CTA

// Augmented f16 centroids (device global scratch; x is converted in-kernel).
//  c row: [ c (64)] [1, 1, c2_hi, c2_lo] [0 x 12]
__device__ __align__(16) uint32_t g_cb[(size_t)Gn * Kn * (RB / 4)];

// Dynamic smem (bytes). Slot = 16KB main (128B rows, XOR swizzle) + 4KB aug
// (32B rows). x resident in slot 0; c triple-buffered in slots 1..3.
constexpr int XS0 = 0;
constexpr int CBB = 20480;           // c buffer stride
constexpr int SMEM_TOTAL = 20480 * 4;   // 81920 B

__device__ __forceinline__ uint32_t smem_u32(const void* p) {
    uint32_t a;
    asm("{ .reg .u64 t; cvta.to.shared.u64 t, %1; cvt.u32.u64 %0, t; }"
        : "=r"(a) : "l"(p));
    return a;
}
__device__ __forceinline__ float fsqrt_approx(float v) {
    float r;
    asm("sqrt.approx.f32 %0, %1;" : "=f"(r) : "f"(v));
    return r;
}
__device__ __forceinline__ uint32_t pack_f16(float lo, float hi) {
    __half2 h = __floats2half2_rn(lo, hi);   // .x = lo (low half)
    uint32_t u;
    memcpy(&u, &h, 4);
    return u;
}
__device__ __forceinline__ void cp16(uint32_t dst, const void* src) {
    asm volatile("cp.async.cg.shared.global [%0], [%1], 16;"
                 :: "r"(dst), "l"(src) : "memory");
}
#define CP_COMMIT() asm volatile("cp.async.commit_group;" ::: "memory")
#define CP_WAIT0()  asm volatile("cp.async.wait_group 0;" ::: "memory")
#define CP_WAIT1()  asm volatile("cp.async.wait_group 1;" ::: "memory")

__device__ __forceinline__ void ldsm_x4(uint32_t r[4], uint32_t addr) {
    asm volatile("ldmatrix.sync.aligned.m8n8.x4.shared.b16 {%0,%1,%2,%3}, [%4];"
                 : "=r"(r[0]), "=r"(r[1]), "=r"(r[2]), "=r"(r[3]) : "r"(addr));
}
// f16 x f16 -> f16 accumulate: D/C in 2 regs (f16x2 each)
__device__ __forceinline__ void mma_f16(uint32_t c[2], const uint32_t a[4],
                                        uint32_t b0, uint32_t b1) {
    asm volatile(
        "mma.sync.aligned.m16n8k16.row.col.f16.f16.f16.f16 "
        "{%0,%1}, {%2,%3,%4,%5}, {%6,%7}, {%0,%1};"
        : "+r"(c[0]), "+r"(c[1])
        : "r"(a[0]), "r"(a[1]), "r"(a[2]), "r"(a[3]), "r"(b0), "r"(b1));
}
__device__ __forceinline__ void stg_cs2(float* p, float a, float b) {
    asm volatile("st.global.cs.v2.f32 [%0], {%1, %2};"
                 :: "l"(p), "f"(a), "f"(b) : "memory");
}
__device__ __forceinline__ void sts128(uint32_t a, uint4 v) {
    asm volatile("st.shared.v4.b32 [%0], {%1,%2,%3,%4};"
                 :: "r"(a), "r"(v.x), "r"(v.y), "r"(v.z), "r"(v.w) : "memory");
}
// aug-tile address: 32B rows; 16B chunk q of row r at flat=(2r+q)^((r>>2)&7)
__device__ __forceinline__ uint32_t t1addr(uint32_t base, int row, int q) {
    return base + (uint32_t)((((row * 2 + q) ^ ((row >> 2) & 7)) << 4));
}

// ---------------------------------------------------------------------------
// Pass 1 (tiny): augmented f16 centroid rows (exact fp32 norms, hi/lo split).
// ---------------------------------------------------------------------------
__global__ __launch_bounds__(256)
void prep_c_kernel(const float* __restrict__ cen)
{
    const int t = blockIdx.x * blockDim.x + threadIdx.x;
    if (t >= Gn * Kn) return;
    const float4* src = (const float4*)(cen + (size_t)t * Dn);
    uint4* dst = (uint4*)(g_cb + (size_t)t * (RB / 4));

    float s = 0.f;
#pragma unroll
    for (int i = 0; i < 8; i++) {
        float4 v0 = src[2 * i];
        float4 v1 = src[2 * i + 1];
        s = fmaf(v0.x, v0.x, s); s = fmaf(v0.y, v0.y, s);
        s = fmaf(v0.z, v0.z, s); s = fmaf(v0.w, v0.w, s);
        s = fmaf(v1.x, v1.x, s); s = fmaf(v1.y, v1.y, s);
        s = fmaf(v1.z, v1.z, s); s = fmaf(v1.w, v1.w, s);
        uint4 o;
        o.x = pack_f16(v0.x, v0.y); o.y = pack_f16(v0.z, v0.w);
        o.z = pack_f16(v1.x, v1.y); o.w = pack_f16(v1.z, v1.w);
        dst[i] = o;
    }
    const float hf  = __half2float(__float2half_rn(s));
    const float res = s - hf;
    uint4 aug;
    aug.x = pack_f16(1.f, 1.f); aug.y = pack_f16(hf, res);
    aug.z = 0u; aug.w = 0u;
    dst[8] = aug;
    dst[9] = make_uint4(0u, 0u, 0u, 0u);
}

// c tile loader: 1280 16B chunks (128 rows x 160B) over 512 threads.
__device__ __forceinline__ void load_ctile(uint32_t base, const char* gsrc, int tid)
{
#pragma unroll
    for (int i = 0; i < 3; i++) {
        const int idx = i * NT + tid;
        if (idx < 1280) {
            const int row = idx / 10;
            const int q   = idx - row * 10;
            const char* src = gsrc + row * RB + q * 16;
            if (q < 8) cp16(base + row * 128 + ((q ^ (row & 7)) << 4), src);
            else       cp16(t1addr(base + 16384, row, q - 8), src);
        }
    }
}

// ---------------------------------------------------------------------------
// Pass 2: x tile resident (converted in-kernel), stream 8 c tiles.
// ---------------------------------------------------------------------------
__global__ __launch_bounds__(NT, 2)
void dist_kernel(const float* __restrict__ x, float* __restrict__ out)
{
    extern __shared__ __align__(128) char smem[];
    const uint32_t sb = smem_u32(smem);

    const int tid  = threadIdx.x;
    const int wid  = tid >> 5;
    const int lane = tid & 31;
    const int qid  = lane >> 2;     // 0..7
    const int t4   = lane & 3;      // 0..3

    const int g  = blockIdx.y;
    const int b0 = blockIdx.x * TM;

    const char* cgb = (const char*)g_cb + (size_t)(g * Kn) * RB;

    // ---- Prologue: issue c tiles 0 and 1 first (overlap with conversion). ----
    load_ctile(sb + CBB, cgb, tid);
    CP_COMMIT();
    load_ctile(sb + 2 * CBB, cgb + (size_t)TN * RB, tid);
    CP_COMMIT();

    // ---- Convert resident x tile: fp32 -> f16 aug, exact fp32 norms. ----
    // 4 threads per row; each reads 16 floats, butterfly-shfl for the norm.
    {
        const int row  = tid >> 2;
        const int part = tid & 3;
        const float4* xr = (const float4*)(x + (size_t)(g * Bn + b0 + row) * Dn)
                           + part * 4;
        float4 v0 = xr[0], v1 = xr[1], v2 = xr[2], v3 = xr[3];
        float s = 0.f;
        s = fmaf(v0.x, v0.x, s); s = fmaf(v0.y, v0.y, s);
        s = fmaf(v0.z, v0.z, s); s = fmaf(v0.w, v0.w, s);
        s = fmaf(v1.x, v1.x, s); s = fmaf(v1.y, v1.y, s);
        s = fmaf(v1.z, v1.z, s); s = fmaf(v1.w, v1.w, s);
        s = fmaf(v2.x, v2.x, s); s = fmaf(v2.y, v2.y, s);
        s = fmaf(v2.z, v2.z, s); s = fmaf(v2.w, v2.w, s);
        s = fmaf(v3.x, v3.x, s); s = fmaf(v3.y, v3.y, s);
        s = fmaf(v3.z, v3.z, s); s = fmaf(v3.w, v3.w, s);
        s += __shfl_xor_sync(0xffffffffu, s, 1);
        s += __shfl_xor_sync(0xffffffffu, s, 2);   // full row norm in all 4 lanes

        // main chunks 2*part, 2*part+1 hold -2x (f16)
        uint4 m0, m1;
        m0.x = pack_f16(-2.f * v0.x, -2.f * v0.y);
        m0.y = pack_f16(-2.f * v0.z, -2.f * v0.w);
        m0.z = pack_f16(-2.f * v1.x, -2.f * v1.y);
        m0.w = pack_f16(-2.f * v1.z, -2.f * v1.w);
        m1.x = pack_f16(-2.f * v2.x, -2.f * v2.y);
        m1.y = pack_f16(-2.f * v2.z, -2.f * v2.w);
        m1.z = pack_f16(-2.f * v3.x, -2.f * v3.y);
        m1.w = pack_f16(-2.f * v3.z, -2.f * v3.w);
        const int q0 = 2 * part, q1 = 2 * part + 1;
        sts128(sb + XS0 + row * 128 + ((q0 ^ (row & 7)) << 4), m0);
        sts128(sb + XS0 + row * 128 + ((q1 ^ (row & 7)) << 4), m1);

        // aug chunks: [x2_hi, x2_lo, 1, 1, 0...] then zeros
        if (part == 0) {
            const float hf  = __half2float(__float2half_rn(s));
            const float res = s - hf;
            uint4 aug;
            aug.x = pack_f16(hf, res); aug.y = pack_f16(1.f, 1.f);
            aug.z = 0u; aug.w = 0u;
            sts128(t1addr(sb + XS0 + 16384, row, 0), aug);
        } else if (part == 1) {
            sts128(t1addr(sb + XS0 + 16384, row, 1), make_uint4(0u, 0u, 0u, 0u));
        }
    }

    const int wm = (wid >> 2) * 32;   // warp m-base: 0/32/64/96
    const int wn = (wid & 3) * 32;    // warp n-base: 0/32/64/96

    // Per-lane ldmatrix geometry.
    const int swz    = lane & 7;
    const int a_row  = lane & 15;                        // + wm + mt*16
    const int a_qoff = lane >> 4;                        // 0/1
    const int b_nrow = ((lane >> 4) << 3) + (lane & 7);  // + wn (+16)
    const int b_qoff = (lane >> 3) & 1;                  // 0/1

    const uint32_t xs0 = sb + XS0;
    const uint32_t xs1 = sb + XS0 + 16384;

    // Rotating c-buffer bases.
    uint32_t ccur = sb + CBB;
    uint32_t cnxt = sb + 2 * CBB;
    uint32_t cpf  = sb + 3 * CBB;

#pragma unroll 1
    for (int ct = 0; ct < NCT; ct++) {
        if (ct == NCT - 1) { CP_WAIT0(); } else { CP_WAIT1(); }
        __syncthreads();   // also orders the x conversion STS on ct==0

        if (ct + 2 < NCT) {
            load_ctile(cpf, cgb + (size_t)(ct + 2) * TN * RB, tid);
            CP_COMMIT();
        }

        const uint32_t cs0 = ccur;
        const uint32_t cs1 = ccur + 16384;

        // acc[mt][nt][h]: f16x2 pair; rows wm+16mt+8h+qid, cols wn+8nt+2t4.
        uint32_t acc[2][4][2];
#pragma unroll
        for (int mt = 0; mt < 2; mt++)
#pragma unroll
            for (int nt = 0; nt < 4; nt++) { acc[mt][nt][0] = 0u; acc[mt][nt][1] = 0u; }

        // ---- k-steps 0..3: main 64 dims. ----
#pragma unroll
        for (int ks = 0; ks < 4; ks++) {
            const uint32_t qa = (uint32_t)(((2 * ks + a_qoff) ^ swz) << 4);
            const uint32_t qb = (uint32_t)(((2 * ks + b_qoff) ^ swz) << 4);

            uint32_t bf[4][2];
            {
                uint32_t r[4];
                ldsm_x4(r, cs0 + (uint32_t)((wn + b_nrow) * 128) + qb);
                bf[0][0] = r[0]; bf[0][1] = r[1]; bf[1][0] = r[2]; bf[1][1] = r[3];
                ldsm_x4(r, cs0 + (uint32_t)((wn + 16 + b_nrow) * 128) + qb);
                bf[2][0] = r[0]; bf[2][1] = r[1]; bf[3][0] = r[2]; bf[3][1] = r[3];
            }
#pragma unroll
            for (int mt = 0; mt < 2; mt++) {
                uint32_t a[4];
                ldsm_x4(a, xs0 + (uint32_t)((wm + mt * 16 + a_row) * 128) + qa);
#pragma unroll
                for (int nt = 0; nt < 4; nt++)
                    mma_f16(acc[mt][nt], a, bf[nt][0], bf[nt][1]);
            }
        }

        // ---- k-step 4: augmented 16 dims. ----
        {
            uint32_t bf[4][2];
            {
                uint32_t r[4];
                ldsm_x4(r, t1addr(cs1, wn + b_nrow, b_qoff));
                bf[0][0] = r[0]; bf[0][1] = r[1]; bf[1][0] = r[2]; bf[1][1] = r[3];
                ldsm_x4(r, t1addr(cs1, wn + 16 + b_nrow, b_qoff));
                bf[2][0] = r[0]; bf[2][1] = r[1]; bf[3][0] = r[2]; bf[3][1] = r[3];
            }
#pragma unroll
            for (int mt = 0; mt < 2; mt++) {
                uint32_t a[4];
                ldsm_x4(a, t1addr(xs1, wm + mt * 16 + a_row, a_qoff));
#pragma unroll
                for (int nt = 0; nt < 4; nt++)
                    mma_f16(acc[mt][nt], a, bf[nt][0], bf[nt][1]);
            }
        }

        // ---- Epilogue: unpack f16 d^2 -> sqrt -> streaming store. ----
        const int k0 = ct * TN;
#pragma unroll
        for (int mt = 0; mt < 2; mt++) {
            const int row0 = b0 + wm + mt * 16 + qid;
            float* opa = out + (size_t)(g * Bn + row0) * Kn + k0 + wn + 2 * t4;
            float* opb = opa + (size_t)8 * Kn;
#pragma unroll
            for (int nt = 0; nt < 4; nt++) {
                __half2 h0, h1;
                memcpy(&h0, &acc[mt][nt][0], 4);
                memcpy(&h1, &acc[mt][nt][1], 4);
                float2 f0 = __half22float2(h0);   // row0:  cols 2t4, 2t4+1
                float2 f1 = __half22float2(h1);   // row0+8
                stg_cs2(opa + nt * 8, fsqrt_approx(f0.x), fsqrt_approx(f0.y));
                stg_cs2(opb + nt * 8, fsqrt_approx(f1.x), fsqrt_approx(f1.y));
            }
        }

        // Rotate c buffers.
        const uint32_t t = ccur;
        ccur = cnxt; cnxt = cpf; cpf = t;
    }
}

extern "C" void kernel_launch(void* const* d_in, const int* in_sizes, int n_in,
                              void* d_out, int out_size)
{
    const float* x   = (const float*)d_in[0];   // [G, B, D] fp32
    const float* cen = (const float*)d_in[1];   // [G, K, D] fp32
    float* out = (float*)d_out;                 // [G, B, K] fp32

    static bool attr_set = false;
    if (!attr_set) {
        cudaFuncSetAttribute(dist_kernel,
                             cudaFuncAttributeMaxDynamicSharedMemorySize, SMEM_TOTAL);
        attr_set = true;
    }

    prep_c_kernel<<<(Gn * Kn + 255) / 256, 256>>>(cen);

    dim3 grid(Bn / TM, Gn);                     // (64, 16) = 1024 CTAs
    dist_kernel<<<grid, NT, SMEM_TOTAL>>>(x, out);
}